// round 11
// baseline (speedup 1.0000x reference)
#include <cuda_runtime.h>
#include <cuda_bf16.h>
#include <cstdint>

#define D_VEC 8              // 32 floats = 8 float4 per node row
#define BUCKET_W 32          // nodes per bucket
#define NB_MAX 3200          // max buckets (n_nodes <= 102400)
#define CAP 1280             // records per bucket (mean 1024 + 8 sigma)

// Scratch (module-static; allocation-free at runtime).
__device__ int2 g_rec[NB_MAX * CAP + 8];
__device__ int  g_bcnt[NB_MAX];

__global__ void zero_out_kernel(float4* __restrict__ out, int n4) {
    int i = blockIdx.x * blockDim.x + threadIdx.x;
    if (i < n4) out[i] = make_float4(0.f, 0.f, 0.f, 0.f);
}

__global__ void zero_cnt_kernel(int nb) {
    int i = blockIdx.x * blockDim.x + threadIdx.x;
    if (i < nb) g_bcnt[i] = 0;
}

__device__ __forceinline__ void red_v4(float4* addr, float4 r) {
    asm volatile("red.global.add.v4.f32 [%0], {%1, %2, %3, %4};"
                 :: "l"(addr), "f"(r.x), "f"(r.y), "f"(r.z), "f"(r.w)
                 : "memory");
}

// Phase A: bin edges by target bucket. 8B record: {sidx | t_local<<20, w}.
__global__ void __launch_bounds__(256)
bin_kernel(const float4* __restrict__ input,
           const int* __restrict__ sidx,
           const int* __restrict__ tidx,
           const float* __restrict__ enorm,
           const float* __restrict__ esgn,
           float4* __restrict__ out,
           int n_edges) {
    int e = blockIdx.x * blockDim.x + threadIdx.x;
    if (e >= n_edges) return;

    int   t = __ldg(tidx + e);
    int   s = __ldg(sidx + e);
    float w = __ldg(esgn + e) * __ldg(enorm + e);

    int b  = t >> 5;           // bucket
    int tl = t & 31;           // node within bucket

    int pos = atomicAdd(&g_bcnt[b], 1);
    if (pos < CAP) {
        g_rec[b * CAP + pos] = make_int2(s | (tl << 20), __float_as_int(w));
    } else {
        // Overflow fallback (statistically never): direct atomic scatter.
        const float4* src = input + s * D_VEC;
        float4*       dst = out   + t * D_VEC;
#pragma unroll
        for (int j = 0; j < D_VEC; j++) {
            float4 v = __ldcg(src + j);
            float4 r;
            r.x = v.x * w; r.y = v.y * w; r.z = v.z * w; r.w = v.w * w;
            red_v4(dst + j, r);
        }
    }
}

// Phase B: one CTA per bucket. 16 private SMEM copies (one per (warp,sub)
// 8-lane group) make simultaneous same-target RMW impossible -> plain
// LDS/FFMA/STS accumulation, no atomics. Final: reduce copies, one red.v4
// per 16B output slot (800K atomics total vs 25.6M in the direct scheme).
__global__ void __launch_bounds__(128)
bucket_accum_kernel(const float4* __restrict__ input,
                    float4* __restrict__ out,
                    int n_nodes) {
    extern __shared__ float4 sm[];   // 16 copies * 256 float4 = 64KB

    int b    = blockIdx.x;
    int tid  = threadIdx.x;
    int wid  = tid >> 5;
    int lane = tid & 31;
    int sub  = lane >> 3;     // which of 4 edge slots in the warp
    int j    = lane & 7;      // float4 slot within the 128B row
    int copy = (wid << 2) | sub;              // 0..15
    float4* my = sm + copy * 256;             // this group's 4KB copy

    // Zero all copies.
    float4 z = make_float4(0.f, 0.f, 0.f, 0.f);
    for (int i = tid; i < 16 * 256; i += 128) sm[i] = z;
    __syncthreads();

    int cnt = g_bcnt[b];
    if (cnt > CAP) cnt = CAP;
    const int2* brec = g_rec + b * CAP;

    // Each warp strides over the bucket; 8 edges per CTA-iter per warp pair.
    for (int base = wid * 8; base < cnt; base += 32) {
        int i0 = base + sub * 2;              // 16B-aligned pair index
        int4 rr = *(const int4*)(brec + i0);  // 2 records (broadcast in group)

        bool v0 = (i0     < cnt);
        bool v1 = (i0 + 1 < cnt);

        int   s0  = v0 ? (rr.x & 0xFFFFF) : 0;
        int   tl0 = v0 ? ((rr.x >> 20) & 31) : 0;
        float w0  = v0 ? __int_as_float(rr.y) : 0.f;
        int   s1  = v1 ? (rr.z & 0xFFFFF) : 0;
        int   tl1 = v1 ? ((rr.z >> 20) & 31) : 0;
        float w1  = v1 ? __int_as_float(rr.w) : 0.f;

        // Two independent gathers in flight per group.
        float4 g0 = __ldcg(input + s0 * D_VEC + j);
        float4 g1 = __ldcg(input + s1 * D_VEC + j);

        // Sequential RMW (program order) -> safe even if tl0 == tl1.
        float4* a0 = my + tl0 * D_VEC + j;
        float4 f0 = *a0;
        f0.x += g0.x * w0; f0.y += g0.y * w0;
        f0.z += g0.z * w0; f0.w += g0.w * w0;
        *a0 = f0;

        float4* a1 = my + tl1 * D_VEC + j;
        float4 f1 = *a1;
        f1.x += g1.x * w1; f1.y += g1.y * w1;
        f1.z += g1.z * w1; f1.w += g1.w * w1;
        *a1 = f1;
    }
    __syncthreads();

    // Reduce the 16 copies and scatter once per 16B slot.
#pragma unroll
    for (int p = tid; p < 256; p += 128) {
        int row = p >> 3;
        int jj  = p & 7;
        float4 acc = z;
#pragma unroll
        for (int c = 0; c < 16; c++) {
            float4 v = sm[c * 256 + p];
            acc.x += v.x; acc.y += v.y; acc.z += v.z; acc.w += v.w;
        }
        int node = b * BUCKET_W + row;
        if (node < n_nodes)
            red_v4(out + node * D_VEC + jj, acc);  // atomic: coexists with overflow path
    }
}

// Legacy direct-atomic kernel (safety fallback for unexpected shapes).
__global__ void __launch_bounds__(256)
legacy_kernel(const float4* __restrict__ input,
              const int* __restrict__ sidx,
              const int* __restrict__ tidx,
              const float* __restrict__ enorm,
              const float* __restrict__ esgn,
              float4* __restrict__ out,
              int n_edges) {
    int gid = blockIdx.x * blockDim.x + threadIdx.x;
    int e = gid >> 3;
    int j = gid & 7;
    if (e >= n_edges) return;
    int   s = __ldg(sidx + e);
    int   t = __ldg(tidx + e);
    float w = __ldg(esgn + e) * __ldg(enorm + e);
    float4 v = __ldg(input + s * D_VEC + j);
    float4 r;
    r.x = v.x * w; r.y = v.y * w; r.z = v.z * w; r.w = v.w * w;
    red_v4(out + t * D_VEC + j, r);
}

extern "C" void kernel_launch(void* const* d_in, const int* in_sizes, int n_in,
                              void* d_out, int out_size) {
    const float4* input = (const float4*)d_in[0];   // [n_nodes, 32] fp32
    const int*    eidx  = (const int*)d_in[1];      // [2, n_edges] int32
    const float*  enorm = (const float*)d_in[2];    // [n_edges]
    const float*  esgn  = (const float*)d_in[3];    // [n_edges]
    float4*       out   = (float4*)d_out;           // [n_nodes, 32] fp32

    int n_edges = in_sizes[2];
    int n_nodes = in_sizes[0] / 32;
    const int* sidx = eidx;
    const int* tidx = eidx + n_edges;

    int n4 = out_size / 4;
    zero_out_kernel<<<(n4 + 255) / 256, 256>>>(out, n4);

    if (n_nodes <= NB_MAX * BUCKET_W) {
        int nb = (n_nodes + BUCKET_W - 1) / BUCKET_W;
        zero_cnt_kernel<<<(nb + 255) / 256, 256>>>(nb);
        bin_kernel<<<(n_edges + 255) / 256, 256>>>(
            input, sidx, tidx, enorm, esgn, out, n_edges);
        cudaFuncSetAttribute(bucket_accum_kernel,
                             cudaFuncAttributeMaxDynamicSharedMemorySize,
                             16 * 256 * sizeof(float4));
        bucket_accum_kernel<<<nb, 128, 16 * 256 * sizeof(float4)>>>(
            input, out, n_nodes);
    } else {
        long long total_threads = (long long)n_edges * D_VEC;
        int blocks = (int)((total_threads + 255) / 256);
        legacy_kernel<<<blocks, 256>>>(
            input, sidx, tidx, enorm, esgn, out, n_edges);
    }
}

// round 12
// speedup vs baseline: 1.3317x; 1.3317x over previous
#include <cuda_runtime.h>
#include <cuda_bf16.h>
#include <cstdint>

#define D_VEC 8              // 32 floats = 8 float4 per node row
#define BUCKET_W 32          // nodes per bucket
#define NB_MAX 3200          // max buckets (n_nodes <= 102400)
#define SUB 8                // sub-segments per bucket (spreads counter atomics)
#define SUBCAP 224           // records per sub-segment (mean 128 + ~8 sigma), even

// Scratch (module-static; allocation-free at runtime). ~46MB records.
__device__ int2 g_rec[NB_MAX * SUB * SUBCAP + 8];
__device__ int  g_bcnt[NB_MAX * SUB];

__global__ void zero_out_kernel(float4* __restrict__ out, int n4) {
    int i = blockIdx.x * blockDim.x + threadIdx.x;
    if (i < n4) out[i] = make_float4(0.f, 0.f, 0.f, 0.f);
}

__global__ void zero_cnt_kernel(int n) {
    int i = blockIdx.x * blockDim.x + threadIdx.x;
    if (i < n) g_bcnt[i] = 0;
}

__device__ __forceinline__ void red_v4(float4* addr, float4 r) {
    asm volatile("red.global.add.v4.f32 [%0], {%1, %2, %3, %4};"
                 :: "l"(addr), "f"(r.x), "f"(r.y), "f"(r.z), "f"(r.w)
                 : "memory");
}

// Phase A: bin edges into (bucket, sub) segments. 4 edges/thread, vector loads.
__global__ void __launch_bounds__(256)
bin_kernel(const float4* __restrict__ input,
           const int4*   __restrict__ sidx4,
           const int4*   __restrict__ tidx4,
           const float4* __restrict__ enorm4,
           const float4* __restrict__ esgn4,
           float4* __restrict__ out,
           int n_quads) {
    int q = blockIdx.x * blockDim.x + threadIdx.x;
    if (q >= n_quads) return;

    int4   s4 = __ldg(sidx4  + q);
    int4   t4 = __ldg(tidx4  + q);
    float4 en = __ldg(enorm4 + q);
    float4 eg = __ldg(esgn4  + q);

    int   ss[4] = {s4.x, s4.y, s4.z, s4.w};
    int   tt[4] = {t4.x, t4.y, t4.z, t4.w};
    float ww[4] = {en.x * eg.x, en.y * eg.y, en.z * eg.z, en.w * eg.w};
    int e0 = q << 2;

#pragma unroll
    for (int i = 0; i < 4; i++) {
        int t  = tt[i];
        int b  = t >> 5;
        int tl = t & 31;
        int c  = b * SUB + ((e0 + i) & (SUB - 1));

        int pos = atomicAdd(&g_bcnt[c], 1);
        if (pos < SUBCAP) {
            g_rec[c * SUBCAP + pos] = make_int2(ss[i] | (tl << 20),
                                                __float_as_int(ww[i]));
        } else {
            // Overflow (statistically never): direct atomic scatter.
            const float4* src = input + ss[i] * D_VEC;
            float4*       dst = out   + t * D_VEC;
            float w = ww[i];
#pragma unroll
            for (int j = 0; j < D_VEC; j++) {
                float4 v = __ldcg(src + j);
                float4 r;
                r.x = v.x * w; r.y = v.y * w; r.z = v.z * w; r.w = v.w * w;
                red_v4(dst + j, r);
            }
        }
    }
}

// Phase B: one CTA (128 thr) per bucket. 16 group-private SMEM copies ->
// atomic-free vector RMW. Each group owns half of one sub-segment; 4 records
// per iteration with all loads in flight (2 record int4s + 4 gathers).
__global__ void __launch_bounds__(128)
bucket_accum_kernel(const float4* __restrict__ input,
                    float4* __restrict__ out,
                    int n_nodes) {
    extern __shared__ float4 sm[];   // 16 copies * 256 float4 = 64KB

    int b    = blockIdx.x;
    int tid  = threadIdx.x;
    int grp  = tid >> 3;              // 0..15
    int j    = tid & 7;               // float4 slot in the 128B row
    int sub  = grp & (SUB - 1);
    int half = grp >> 3;              // 0 or 1
    float4* my = sm + grp * 256;

    float4 z = make_float4(0.f, 0.f, 0.f, 0.f);
    for (int i = tid; i < 16 * 256; i += 128) sm[i] = z;
    __syncthreads();

    int c   = b * SUB + sub;
    int cnt = g_bcnt[c];
    if (cnt > SUBCAP) cnt = SUBCAP;
    const int2* base = g_rec + c * SUBCAP;

    int h   = ((cnt + 3) >> 2) << 1;          // even split point ~cnt/2
    int beg = half ? h : 0;
    int end = half ? cnt : (h < cnt ? h : cnt);

    for (int k = beg; k < end; k += 4) {
        // 2 independent record loads (k is even; base is 16B-aligned).
        int4 ra = *(const int4*)(base + k);
        int4 rb = *(const int4*)(base + k + 2);   // padded tail in g_rec

        int   rs[4], rt[4];
        float rw[4];
        rs[0] = ra.x & 0xFFFFF; rt[0] = (ra.x >> 20) & 31;
        rw[0] = __int_as_float(ra.y);
        rs[1] = ra.z & 0xFFFFF; rt[1] = (ra.z >> 20) & 31;
        rw[1] = (k + 1 < end) ? __int_as_float(ra.w) : 0.f;
        rs[2] = rb.x & 0xFFFFF; rt[2] = (rb.x >> 20) & 31;
        rw[2] = (k + 2 < end) ? __int_as_float(rb.y) : 0.f;
        rs[3] = rb.z & 0xFFFFF; rt[3] = (rb.z >> 20) & 31;
        rw[3] = (k + 3 < end) ? __int_as_float(rb.w) : 0.f;

        // 4 independent gathers in flight.
        float4 g0 = __ldg(input + rs[0] * D_VEC + j);
        float4 g1 = __ldg(input + rs[1] * D_VEC + j);
        float4 g2 = __ldg(input + rs[2] * D_VEC + j);
        float4 g3 = __ldg(input + rs[3] * D_VEC + j);

        // Sequential (program-order) RMW into the private copy — safe
        // even when records share a target row.
        float4* a;
        float4 f;
#define ACC(G, I)                                                \
        a = my + rt[I] * D_VEC + j;                              \
        f = *a;                                                  \
        f.x += (G).x * rw[I]; f.y += (G).y * rw[I];              \
        f.z += (G).z * rw[I]; f.w += (G).w * rw[I];              \
        *a = f;
        ACC(g0, 0) ACC(g1, 1) ACC(g2, 2) ACC(g3, 3)
#undef ACC
    }
    __syncthreads();

    // Reduce the 16 copies; one red.v4 per 16B slot (coexists with overflow).
    for (int p = tid; p < 256; p += 128) {
        int row = p >> 3;
        int jj  = p & 7;
        float4 acc = z;
#pragma unroll
        for (int cpy = 0; cpy < 16; cpy++) {
            float4 v = sm[cpy * 256 + p];
            acc.x += v.x; acc.y += v.y; acc.z += v.z; acc.w += v.w;
        }
        int node = b * BUCKET_W + row;
        if (node < n_nodes)
            red_v4(out + node * D_VEC + jj, acc);
    }
}

// Direct-atomic kernel (fallback for unexpected shapes / edge tail).
__global__ void __launch_bounds__(256)
legacy_kernel(const float4* __restrict__ input,
              const int* __restrict__ sidx,
              const int* __restrict__ tidx,
              const float* __restrict__ enorm,
              const float* __restrict__ esgn,
              float4* __restrict__ out,
              int e_beg, int n_edges) {
    int gid = blockIdx.x * blockDim.x + threadIdx.x;
    int e = e_beg + (gid >> 3);
    int j = gid & 7;
    if (e >= n_edges) return;
    int   s = __ldg(sidx + e);
    int   t = __ldg(tidx + e);
    float w = __ldg(esgn + e) * __ldg(enorm + e);
    float4 v = __ldg(input + s * D_VEC + j);
    float4 r;
    r.x = v.x * w; r.y = v.y * w; r.z = v.z * w; r.w = v.w * w;
    red_v4(out + t * D_VEC + j, r);
}

extern "C" void kernel_launch(void* const* d_in, const int* in_sizes, int n_in,
                              void* d_out, int out_size) {
    const float4* input = (const float4*)d_in[0];   // [n_nodes, 32] fp32
    const int*    eidx  = (const int*)d_in[1];      // [2, n_edges] int32
    const float*  enorm = (const float*)d_in[2];    // [n_edges]
    const float*  esgn  = (const float*)d_in[3];    // [n_edges]
    float4*       out   = (float4*)d_out;           // [n_nodes, 32] fp32

    int n_edges = in_sizes[2];
    int n_nodes = in_sizes[0] / 32;
    const int* sidx = eidx;
    const int* tidx = eidx + n_edges;

    int n4 = out_size / 4;
    zero_out_kernel<<<(n4 + 255) / 256, 256>>>(out, n4);

    if (n_nodes <= NB_MAX * BUCKET_W) {
        int nb   = (n_nodes + BUCKET_W - 1) / BUCKET_W;
        int ncnt = nb * SUB;
        zero_cnt_kernel<<<(ncnt + 255) / 256, 256>>>(ncnt);

        int n_quads = n_edges >> 2;
        bin_kernel<<<(n_quads + 255) / 256, 256>>>(
            input, (const int4*)sidx, (const int4*)tidx,
            (const float4*)enorm, (const float4*)esgn,
            out, n_quads);

        int tail = n_quads << 2;
        if (tail < n_edges) {
            int rem = n_edges - tail;
            legacy_kernel<<<(rem * D_VEC + 255) / 256, 256>>>(
                input, sidx, tidx, enorm, esgn, out, tail, n_edges);
        }

        cudaFuncSetAttribute(bucket_accum_kernel,
                             cudaFuncAttributeMaxDynamicSharedMemorySize,
                             16 * 256 * sizeof(float4));
        bucket_accum_kernel<<<nb, 128, 16 * 256 * sizeof(float4)>>>(
            input, out, n_nodes);
    } else {
        legacy_kernel<<<(int)(((long long)n_edges * D_VEC + 255) / 256), 256>>>(
            input, sidx, tidx, enorm, esgn, out, 0, n_edges);
    }
}

// round 13
// speedup vs baseline: 1.6632x; 1.2489x over previous
#include <cuda_runtime.h>
#include <cuda_bf16.h>
#include <cstdint>

#define D_VEC 8              // 32 floats = 8 float4 per node row
#define BUCKET_W 32          // nodes per bucket
#define NB_MAX 3200          // max buckets (n_nodes <= 102400)
#define SUB 8                // sub-segments per bucket
#define SUBCAP 224           // records per sub-segment (mean 128 + ~8.5 sigma)

// Scratch (module-static; allocation-free at runtime). ~46MB records.
__device__ int2 g_rec[NB_MAX * SUB * SUBCAP + 8];
__device__ int  g_bcnt[NB_MAX * SUB];

__global__ void zero_out_kernel(float4* __restrict__ out, int n4) {
    int i = blockIdx.x * blockDim.x + threadIdx.x;
    if (i < n4) out[i] = make_float4(0.f, 0.f, 0.f, 0.f);
}

__global__ void zero_cnt_kernel(int n) {
    int i = blockIdx.x * blockDim.x + threadIdx.x;
    if (i < n) g_bcnt[i] = 0;
}

__device__ __forceinline__ void red_v4(float4* addr, float4 r) {
    asm volatile("red.global.add.v4.f32 [%0], {%1, %2, %3, %4};"
                 :: "l"(addr), "f"(r.x), "f"(r.y), "f"(r.z), "f"(r.w)
                 : "memory");
}

// Phase A: bin edges into (bucket, sub) segments. 8 edges/thread; the 8
// edges of an oct deterministically go to sub-counters 0..7 (perfect spread),
// and all 8 counter atomics are independent (ILP=8).
__global__ void __launch_bounds__(256)
bin_kernel(const float4* __restrict__ input,
           const int4*   __restrict__ sidx4,
           const int4*   __restrict__ tidx4,
           const float4* __restrict__ enorm4,
           const float4* __restrict__ esgn4,
           float4* __restrict__ out,
           int n_octs) {
    int o = blockIdx.x * blockDim.x + threadIdx.x;
    if (o >= n_octs) return;

    int4   s0 = __ldg(sidx4  + 2 * o);
    int4   s1 = __ldg(sidx4  + 2 * o + 1);
    int4   t0 = __ldg(tidx4  + 2 * o);
    int4   t1 = __ldg(tidx4  + 2 * o + 1);
    float4 en0 = __ldg(enorm4 + 2 * o);
    float4 en1 = __ldg(enorm4 + 2 * o + 1);
    float4 eg0 = __ldg(esgn4  + 2 * o);
    float4 eg1 = __ldg(esgn4  + 2 * o + 1);

    int   ss[8] = {s0.x, s0.y, s0.z, s0.w, s1.x, s1.y, s1.z, s1.w};
    int   tt[8] = {t0.x, t0.y, t0.z, t0.w, t1.x, t1.y, t1.z, t1.w};
    float ww[8] = {en0.x * eg0.x, en0.y * eg0.y, en0.z * eg0.z, en0.w * eg0.w,
                   en1.x * eg1.x, en1.y * eg1.y, en1.z * eg1.z, en1.w * eg1.w};

    int pos[8], cc[8];
#pragma unroll
    for (int i = 0; i < 8; i++) {
        cc[i]  = (tt[i] >> 5) * SUB + i;          // bucket*SUB + sub(=i)
        pos[i] = atomicAdd(&g_bcnt[cc[i]], 1);    // 8 independent chains
    }

#pragma unroll
    for (int i = 0; i < 8; i++) {
        int tl = tt[i] & 31;
        if (pos[i] < SUBCAP) {
            g_rec[cc[i] * SUBCAP + pos[i]] =
                make_int2(ss[i] | (tl << 20), __float_as_int(ww[i]));
        } else {
            // Overflow (statistically never): direct atomic scatter.
            const float4* src = input + ss[i] * D_VEC;
            float4*       dst = out   + tt[i] * D_VEC;
            float w = ww[i];
#pragma unroll
            for (int j = 0; j < D_VEC; j++) {
                float4 v = __ldcg(src + j);
                float4 r;
                r.x = v.x * w; r.y = v.y * w; r.z = v.z * w; r.w = v.w * w;
                red_v4(dst + j, r);
            }
        }
    }
}

// Phase B: one CTA (128 thr) per bucket; 16 group-private SMEM copies ->
// atomic-free accumulation. launch_bounds(128,3) grants ~170 regs/thread so
// 8 gathers + 4 record loads stay in flight per iteration (the R12 version
// was throttled to 32 regs, serializing everything).
__global__ void __launch_bounds__(128, 3)
bucket_accum_kernel(const float4* __restrict__ input,
                    float4* __restrict__ out,
                    int n_nodes) {
    extern __shared__ float4 sm[];   // 16 copies * 256 float4 = 64KB

    int b    = blockIdx.x;
    int tid  = threadIdx.x;
    int grp  = tid >> 3;              // 0..15
    int j    = tid & 7;               // float4 slot in the 128B row
    int sub  = grp & (SUB - 1);
    int half = grp >> 3;              // 0 or 1
    float4* my = sm + grp * 256;

    float4 z = make_float4(0.f, 0.f, 0.f, 0.f);
    for (int i = tid; i < 16 * 256; i += 128) sm[i] = z;
    __syncthreads();

    int c   = b * SUB + sub;
    int cnt = g_bcnt[c];
    if (cnt > SUBCAP) cnt = SUBCAP;
    const int2* base = g_rec + c * SUBCAP;

    int h   = ((cnt + 15) >> 4) << 3;        // ~cnt/2, multiple of 8
    int beg = half ? h : 0;
    int end = half ? cnt : (h < cnt ? h : cnt);

    for (int k = beg; k < end; k += 8) {
        // 4 independent record loads (32B window, 16B-aligned).
        int4 ra = *(const int4*)(base + k);
        int4 rb = *(const int4*)(base + k + 2);
        int4 rc = *(const int4*)(base + k + 4);
        int4 rd = *(const int4*)(base + k + 6);

        int raw_s[8] = {ra.x, ra.z, rb.x, rb.z, rc.x, rc.z, rd.x, rd.z};
        int raw_w[8] = {ra.y, ra.w, rb.y, rb.w, rc.y, rc.w, rd.y, rd.w};

        int   rs[8], rt[8];
        float rw[8];
#pragma unroll
        for (int i = 0; i < 8; i++) {
            bool valid = (k + i < end);
            rs[i] = valid ? (raw_s[i] & 0xFFFFF) : 0;   // bound the gather
            rt[i] = (raw_s[i] >> 20) & 31;
            rw[i] = valid ? __int_as_float(raw_w[i]) : 0.f;
        }

        // 8 independent gathers in flight.
        float4 g[8];
#pragma unroll
        for (int i = 0; i < 8; i++)
            g[i] = __ldcg(input + rs[i] * D_VEC + j);

        // Sequential (program-order) RMW into the private copy — safe
        // even when records share a target row.
#pragma unroll
        for (int i = 0; i < 8; i++) {
            float4* a = my + rt[i] * D_VEC + j;
            float4 f = *a;
            f.x += g[i].x * rw[i]; f.y += g[i].y * rw[i];
            f.z += g[i].z * rw[i]; f.w += g[i].w * rw[i];
            *a = f;
        }
    }
    __syncthreads();

    // Reduce the 16 copies; one red.v4 per 16B slot (coexists with overflow).
    for (int p = tid; p < 256; p += 128) {
        int row = p >> 3;
        int jj  = p & 7;
        float4 acc = z;
#pragma unroll
        for (int cpy = 0; cpy < 16; cpy++) {
            float4 v = sm[cpy * 256 + p];
            acc.x += v.x; acc.y += v.y; acc.z += v.z; acc.w += v.w;
        }
        int node = b * BUCKET_W + row;
        if (node < n_nodes)
            red_v4(out + node * D_VEC + jj, acc);
    }
}

// Direct-atomic kernel (fallback for unexpected shapes / edge tail).
__global__ void __launch_bounds__(256)
legacy_kernel(const float4* __restrict__ input,
              const int* __restrict__ sidx,
              const int* __restrict__ tidx,
              const float* __restrict__ enorm,
              const float* __restrict__ esgn,
              float4* __restrict__ out,
              int e_beg, int n_edges) {
    int gid = blockIdx.x * blockDim.x + threadIdx.x;
    int e = e_beg + (gid >> 3);
    int j = gid & 7;
    if (e >= n_edges) return;
    int   s = __ldg(sidx + e);
    int   t = __ldg(tidx + e);
    float w = __ldg(esgn + e) * __ldg(enorm + e);
    float4 v = __ldg(input + s * D_VEC + j);
    float4 r;
    r.x = v.x * w; r.y = v.y * w; r.z = v.z * w; r.w = v.w * w;
    red_v4(out + t * D_VEC + j, r);
}

extern "C" void kernel_launch(void* const* d_in, const int* in_sizes, int n_in,
                              void* d_out, int out_size) {
    const float4* input = (const float4*)d_in[0];   // [n_nodes, 32] fp32
    const int*    eidx  = (const int*)d_in[1];      // [2, n_edges] int32
    const float*  enorm = (const float*)d_in[2];    // [n_edges]
    const float*  esgn  = (const float*)d_in[3];    // [n_edges]
    float4*       out   = (float4*)d_out;           // [n_nodes, 32] fp32

    int n_edges = in_sizes[2];
    int n_nodes = in_sizes[0] / 32;
    const int* sidx = eidx;
    const int* tidx = eidx + n_edges;

    int n4 = out_size / 4;
    zero_out_kernel<<<(n4 + 255) / 256, 256>>>(out, n4);

    if (n_nodes <= NB_MAX * BUCKET_W && (n_edges & 7) == 0) {
        int nb   = (n_nodes + BUCKET_W - 1) / BUCKET_W;
        int ncnt = nb * SUB;
        zero_cnt_kernel<<<(ncnt + 255) / 256, 256>>>(ncnt);

        int n_octs = n_edges >> 3;
        bin_kernel<<<(n_octs + 255) / 256, 256>>>(
            input, (const int4*)sidx, (const int4*)tidx,
            (const float4*)enorm, (const float4*)esgn,
            out, n_octs);

        cudaFuncSetAttribute(bucket_accum_kernel,
                             cudaFuncAttributeMaxDynamicSharedMemorySize,
                             16 * 256 * sizeof(float4));
        bucket_accum_kernel<<<nb, 128, 16 * 256 * sizeof(float4)>>>(
            input, out, n_nodes);
    } else {
        legacy_kernel<<<(int)(((long long)n_edges * D_VEC + 255) / 256), 256>>>(
            input, sidx, tidx, enorm, esgn, out, 0, n_edges);
    }
}

// round 14
// speedup vs baseline: 2.1960x; 1.3204x over previous
#include <cuda_runtime.h>
#include <cuda_bf16.h>
#include <cstdint>

#define D_VEC 8              // 32 floats = 8 float4 per node row
#define N_MAX 102400         // max nodes supported by scratch
#define CAP 88               // records per node (mean 32 + ~10 sigma), even

// Scratch (module-static; allocation-free at runtime). ~72MB records.
__device__ int2 g_rec[(size_t)N_MAX * CAP + 8];
__device__ int  g_cnt[N_MAX];

__global__ void zero_out_kernel(float4* __restrict__ out, int n4) {
    int i = blockIdx.x * blockDim.x + threadIdx.x;
    if (i < n4) out[i] = make_float4(0.f, 0.f, 0.f, 0.f);
}

__global__ void zero_cnt_kernel(int n) {
    int i = blockIdx.x * blockDim.x + threadIdx.x;
    if (i < n) g_cnt[i] = 0;
}

__device__ __forceinline__ void red_v4(float4* addr, float4 r) {
    asm volatile("red.global.add.v4.f32 [%0], {%1, %2, %3, %4};"
                 :: "l"(addr), "f"(r.x), "f"(r.y), "f"(r.z), "f"(r.w)
                 : "memory");
}

// Phase A: bin edges by TARGET NODE. 8 edges/thread, vector metadata loads,
// 8 independent counter atomics in flight (100K counters -> ~32 ops/addr,
// well spread across LTS slices).
__global__ void __launch_bounds__(256)
bin_kernel(const float4* __restrict__ input,
           const int4*   __restrict__ sidx4,
           const int4*   __restrict__ tidx4,
           const float4* __restrict__ enorm4,
           const float4* __restrict__ esgn4,
           float4* __restrict__ out,
           int n_octs) {
    int o = blockIdx.x * blockDim.x + threadIdx.x;
    if (o >= n_octs) return;

    int4   s0 = __ldg(sidx4  + 2 * o);
    int4   s1 = __ldg(sidx4  + 2 * o + 1);
    int4   t0 = __ldg(tidx4  + 2 * o);
    int4   t1 = __ldg(tidx4  + 2 * o + 1);
    float4 en0 = __ldg(enorm4 + 2 * o);
    float4 en1 = __ldg(enorm4 + 2 * o + 1);
    float4 eg0 = __ldg(esgn4  + 2 * o);
    float4 eg1 = __ldg(esgn4  + 2 * o + 1);

    int   ss[8] = {s0.x, s0.y, s0.z, s0.w, s1.x, s1.y, s1.z, s1.w};
    int   tt[8] = {t0.x, t0.y, t0.z, t0.w, t1.x, t1.y, t1.z, t1.w};
    float ww[8] = {en0.x * eg0.x, en0.y * eg0.y, en0.z * eg0.z, en0.w * eg0.w,
                   en1.x * eg1.x, en1.y * eg1.y, en1.z * eg1.z, en1.w * eg1.w};

    int pos[8];
#pragma unroll
    for (int i = 0; i < 8; i++)
        pos[i] = atomicAdd(&g_cnt[tt[i]], 1);      // 8 independent chains

#pragma unroll
    for (int i = 0; i < 8; i++) {
        if (pos[i] < CAP) {
            g_rec[(size_t)tt[i] * CAP + pos[i]] =
                make_int2(ss[i], __float_as_int(ww[i]));
        } else {
            // Overflow (statistically never): direct atomic scatter.
            const float4* src = input + ss[i] * D_VEC;
            float4*       dst = out   + tt[i] * D_VEC;
            float w = ww[i];
#pragma unroll
            for (int j = 0; j < D_VEC; j++) {
                float4 v = __ldcg(src + j);
                float4 r;
                r.x = v.x * w; r.y = v.y * w; r.z = v.z * w; r.w = v.w * w;
                red_v4(dst + j, r);
            }
        }
    }
}

// Phase B: one 8-lane group per NODE, accumulator in registers, no SMEM.
// 4 records per iteration: 2 broadcast int4 record loads + 4 independent
// gathers in flight. Single red.v4 writeout per lane (coexists with the
// overflow path's atomics).
__global__ void __launch_bounds__(128)
node_accum_kernel(const float4* __restrict__ input,
                  float4* __restrict__ out,
                  int n_nodes) {
    int gid  = blockIdx.x * blockDim.x + threadIdx.x;
    int node = gid >> 3;
    int j    = gid & 7;
    if (node >= n_nodes) return;

    int cnt = g_cnt[node];
    if (cnt > CAP) cnt = CAP;
    const int2* base = g_rec + (size_t)node * CAP;

    float4 acc = make_float4(0.f, 0.f, 0.f, 0.f);

    for (int k = 0; k < cnt; k += 4) {
        // 2 independent 16B record loads (broadcast within the group).
        int4 ra = __ldcg((const int4*)(base + k));
        int4 rb = __ldcg((const int4*)(base + k + 2));   // within CAP (even)

        int   rs[4];
        float rw[4];
        rs[0] = ra.x;
        rw[0] = __int_as_float(ra.y);
        rs[1] = (k + 1 < cnt) ? ra.z : 0;
        rw[1] = (k + 1 < cnt) ? __int_as_float(ra.w) : 0.f;
        rs[2] = (k + 2 < cnt) ? rb.x : 0;
        rw[2] = (k + 2 < cnt) ? __int_as_float(rb.y) : 0.f;
        rs[3] = (k + 3 < cnt) ? rb.z : 0;
        rw[3] = (k + 3 < cnt) ? __int_as_float(rb.w) : 0.f;

        // 4 independent gathers in flight.
        float4 g0 = __ldcg(input + (size_t)rs[0] * D_VEC + j);
        float4 g1 = __ldcg(input + (size_t)rs[1] * D_VEC + j);
        float4 g2 = __ldcg(input + (size_t)rs[2] * D_VEC + j);
        float4 g3 = __ldcg(input + (size_t)rs[3] * D_VEC + j);

        acc.x += g0.x * rw[0]; acc.y += g0.y * rw[0];
        acc.z += g0.z * rw[0]; acc.w += g0.w * rw[0];
        acc.x += g1.x * rw[1]; acc.y += g1.y * rw[1];
        acc.z += g1.z * rw[1]; acc.w += g1.w * rw[1];
        acc.x += g2.x * rw[2]; acc.y += g2.y * rw[2];
        acc.z += g2.z * rw[2]; acc.w += g2.w * rw[2];
        acc.x += g3.x * rw[3]; acc.y += g3.y * rw[3];
        acc.z += g3.z * rw[3]; acc.w += g3.w * rw[3];
    }

    if (cnt > 0)
        red_v4(out + (size_t)node * D_VEC + j, acc);
}

// Direct-atomic kernel (fallback for unexpected shapes).
__global__ void __launch_bounds__(256)
legacy_kernel(const float4* __restrict__ input,
              const int* __restrict__ sidx,
              const int* __restrict__ tidx,
              const float* __restrict__ enorm,
              const float* __restrict__ esgn,
              float4* __restrict__ out,
              int n_edges) {
    int gid = blockIdx.x * blockDim.x + threadIdx.x;
    int e = gid >> 3;
    int j = gid & 7;
    if (e >= n_edges) return;
    int   s = __ldg(sidx + e);
    int   t = __ldg(tidx + e);
    float w = __ldg(esgn + e) * __ldg(enorm + e);
    float4 v = __ldg(input + (size_t)s * D_VEC + j);
    float4 r;
    r.x = v.x * w; r.y = v.y * w; r.z = v.z * w; r.w = v.w * w;
    red_v4(out + (size_t)t * D_VEC + j, r);
}

extern "C" void kernel_launch(void* const* d_in, const int* in_sizes, int n_in,
                              void* d_out, int out_size) {
    const float4* input = (const float4*)d_in[0];   // [n_nodes, 32] fp32
    const int*    eidx  = (const int*)d_in[1];      // [2, n_edges] int32
    const float*  enorm = (const float*)d_in[2];    // [n_edges]
    const float*  esgn  = (const float*)d_in[3];    // [n_edges]
    float4*       out   = (float4*)d_out;           // [n_nodes, 32] fp32

    int n_edges = in_sizes[2];
    int n_nodes = in_sizes[0] / 32;
    const int* sidx = eidx;
    const int* tidx = eidx + n_edges;

    int n4 = out_size / 4;
    zero_out_kernel<<<(n4 + 255) / 256, 256>>>(out, n4);

    if (n_nodes <= N_MAX && (n_edges & 7) == 0) {
        zero_cnt_kernel<<<(n_nodes + 255) / 256, 256>>>(n_nodes);

        int n_octs = n_edges >> 3;
        bin_kernel<<<(n_octs + 255) / 256, 256>>>(
            input, (const int4*)sidx, (const int4*)tidx,
            (const float4*)enorm, (const float4*)esgn,
            out, n_octs);

        long long total_threads = (long long)n_nodes * D_VEC;
        int blocks = (int)((total_threads + 127) / 128);
        node_accum_kernel<<<blocks, 128>>>(input, out, n_nodes);
    } else {
        legacy_kernel<<<(int)(((long long)n_edges * D_VEC + 255) / 256), 256>>>(
            input, sidx, tidx, enorm, esgn, out, n_edges);
    }
}

// round 15
// speedup vs baseline: 2.2302x; 1.0156x over previous
#include <cuda_runtime.h>
#include <cuda_bf16.h>
#include <cstdint>

#define D_VEC 8              // 32 floats = 8 float4 per node row
#define N_MAX 102400         // max nodes supported by scratch
#define CAP 88               // records per node (mean 32 + ~10 sigma), even

// Scratch (module-static; allocation-free at runtime). ~72MB records.
__device__ int2 g_rec[(size_t)N_MAX * CAP + 8];
__device__ int  g_cnt[N_MAX];

__global__ void zero_kernel(float4* __restrict__ out, int n4, int n_nodes) {
    int i = blockIdx.x * blockDim.x + threadIdx.x;
    if (i < n4) out[i] = make_float4(0.f, 0.f, 0.f, 0.f);
    if (i < n_nodes) g_cnt[i] = 0;
}

__device__ __forceinline__ void red_v4(float4* addr, float4 r) {
    asm volatile("red.global.add.v4.f32 [%0], {%1, %2, %3, %4};"
                 :: "l"(addr), "f"(r.x), "f"(r.y), "f"(r.z), "f"(r.w)
                 : "memory");
}

// Phase A: bin edges by TARGET NODE. 4 edges/thread; per-array metadata is
// one 16B vector per thread (perfectly coalesced), 4 independent counter
// atomics + 4 record stores in flight. 800K threads hide the
// metadata->atomic->store chain.
__global__ void __launch_bounds__(256)
bin_kernel(const float4* __restrict__ input,
           const int4*   __restrict__ sidx4,
           const int4*   __restrict__ tidx4,
           const float4* __restrict__ enorm4,
           const float4* __restrict__ esgn4,
           float4* __restrict__ out,
           int n_quads) {
    int q = blockIdx.x * blockDim.x + threadIdx.x;
    if (q >= n_quads) return;

    int4   s4 = __ldg(sidx4  + q);
    int4   t4 = __ldg(tidx4  + q);
    float4 en = __ldg(enorm4 + q);
    float4 eg = __ldg(esgn4  + q);

    int   ss[4] = {s4.x, s4.y, s4.z, s4.w};
    int   tt[4] = {t4.x, t4.y, t4.z, t4.w};
    float ww[4] = {en.x * eg.x, en.y * eg.y, en.z * eg.z, en.w * eg.w};

    int pos[4];
#pragma unroll
    for (int i = 0; i < 4; i++)
        pos[i] = atomicAdd(&g_cnt[tt[i]], 1);   // 4 independent chains

#pragma unroll
    for (int i = 0; i < 4; i++) {
        if (pos[i] < CAP) {
            g_rec[(size_t)tt[i] * CAP + pos[i]] =
                make_int2(ss[i], __float_as_int(ww[i]));
        } else {
            // Overflow (statistically never): direct atomic scatter.
            const float4* src = input + (size_t)ss[i] * D_VEC;
            float4*       dst = out   + (size_t)tt[i] * D_VEC;
            float w = ww[i];
#pragma unroll
            for (int j = 0; j < D_VEC; j++) {
                float4 v = __ldcg(src + j);
                float4 r;
                r.x = v.x * w; r.y = v.y * w; r.z = v.z * w; r.w = v.w * w;
                red_v4(dst + j, r);
            }
        }
    }
}

// Phase B: one 8-lane group per NODE, register accumulator, no SMEM.
// Record loads are double-buffered (prefetched one iteration ahead) so the
// exposed per-iteration latency is the gather only. Writeout is a plain
// STG.128 for normal nodes (no atomics); overflow nodes red_v4 on the
// zeroed base so bin-time overflow REDs are preserved.
__global__ void __launch_bounds__(256)
node_accum_kernel(const float4* __restrict__ input,
                  float4* __restrict__ out,
                  int n_nodes) {
    int gid  = blockIdx.x * blockDim.x + threadIdx.x;
    int node = gid >> 3;
    int j    = gid & 7;
    if (node >= n_nodes) return;

    int raw = g_cnt[node];
    int cnt = raw > CAP ? CAP : raw;
    const int2* base = g_rec + (size_t)node * CAP;

    float4 acc = make_float4(0.f, 0.f, 0.f, 0.f);

    int4 ra = make_int4(0, 0, 0, 0), rb = make_int4(0, 0, 0, 0);
    if (cnt > 0) {
        ra = __ldcg((const int4*)(base));
        rb = __ldcg((const int4*)(base + 2));   // within CAP (even)
    }

    for (int k = 0; k < cnt; k += 4) {
        // Prefetch next iteration's records (arrive under current gathers).
        int4 na = ra, nb = rb;
        int kn = k + 4;
        if (kn < cnt) {
            na = __ldcg((const int4*)(base + kn));
            nb = __ldcg((const int4*)(base + kn + 2));
        }

        int   rs[4];
        float rw[4];
        rs[0] = ra.x;
        rw[0] = __int_as_float(ra.y);
        rs[1] = (k + 1 < cnt) ? ra.z : 0;
        rw[1] = (k + 1 < cnt) ? __int_as_float(ra.w) : 0.f;
        rs[2] = (k + 2 < cnt) ? rb.x : 0;
        rw[2] = (k + 2 < cnt) ? __int_as_float(rb.y) : 0.f;
        rs[3] = (k + 3 < cnt) ? rb.z : 0;
        rw[3] = (k + 3 < cnt) ? __int_as_float(rb.w) : 0.f;

        // 4 independent gathers in flight.
        float4 g0 = __ldcg(input + (size_t)rs[0] * D_VEC + j);
        float4 g1 = __ldcg(input + (size_t)rs[1] * D_VEC + j);
        float4 g2 = __ldcg(input + (size_t)rs[2] * D_VEC + j);
        float4 g3 = __ldcg(input + (size_t)rs[3] * D_VEC + j);

        acc.x += g0.x * rw[0]; acc.y += g0.y * rw[0];
        acc.z += g0.z * rw[0]; acc.w += g0.w * rw[0];
        acc.x += g1.x * rw[1]; acc.y += g1.y * rw[1];
        acc.z += g1.z * rw[1]; acc.w += g1.w * rw[1];
        acc.x += g2.x * rw[2]; acc.y += g2.y * rw[2];
        acc.z += g2.z * rw[2]; acc.w += g2.w * rw[2];
        acc.x += g3.x * rw[3]; acc.y += g3.y * rw[3];
        acc.z += g3.z * rw[3]; acc.w += g3.w * rw[3];

        ra = na; rb = nb;
    }

    float4* dst = out + (size_t)node * D_VEC + j;
    if (raw > CAP) {
        red_v4(dst, acc);            // coexists with bin's overflow REDs
    } else {
        *dst = acc;                  // exclusive owner: plain STG.128
    }
}

// Direct-atomic kernel (fallback for unexpected shapes).
__global__ void __launch_bounds__(256)
legacy_kernel(const float4* __restrict__ input,
              const int* __restrict__ sidx,
              const int* __restrict__ tidx,
              const float* __restrict__ enorm,
              const float* __restrict__ esgn,
              float4* __restrict__ out,
              int n_edges) {
    int gid = blockIdx.x * blockDim.x + threadIdx.x;
    int e = gid >> 3;
    int j = gid & 7;
    if (e >= n_edges) return;
    int   s = __ldg(sidx + e);
    int   t = __ldg(tidx + e);
    float w = __ldg(esgn + e) * __ldg(enorm + e);
    float4 v = __ldg(input + (size_t)s * D_VEC + j);
    float4 r;
    r.x = v.x * w; r.y = v.y * w; r.z = v.z * w; r.w = v.w * w;
    red_v4(out + (size_t)t * D_VEC + j, r);
}

extern "C" void kernel_launch(void* const* d_in, const int* in_sizes, int n_in,
                              void* d_out, int out_size) {
    const float4* input = (const float4*)d_in[0];   // [n_nodes, 32] fp32
    const int*    eidx  = (const int*)d_in[1];      // [2, n_edges] int32
    const float*  enorm = (const float*)d_in[2];    // [n_edges]
    const float*  esgn  = (const float*)d_in[3];    // [n_edges]
    float4*       out   = (float4*)d_out;           // [n_nodes, 32] fp32

    int n_edges = in_sizes[2];
    int n_nodes = in_sizes[0] / 32;
    const int* sidx = eidx;
    const int* tidx = eidx + n_edges;

    int n4 = out_size / 4;

    if (n_nodes <= N_MAX && (n_edges & 3) == 0) {
        int zmax = n4 > n_nodes ? n4 : n_nodes;
        zero_kernel<<<(zmax + 255) / 256, 256>>>(out, n4, n_nodes);

        int n_quads = n_edges >> 2;
        bin_kernel<<<(n_quads + 255) / 256, 256>>>(
            input, (const int4*)sidx, (const int4*)tidx,
            (const float4*)enorm, (const float4*)esgn,
            out, n_quads);

        long long total_threads = (long long)n_nodes * D_VEC;
        int blocks = (int)((total_threads + 255) / 256);
        node_accum_kernel<<<blocks, 256>>>(input, out, n_nodes);
    } else {
        zero_kernel<<<(n4 + 255) / 256, 256>>>(out, n4, 0);
        legacy_kernel<<<(int)(((long long)n_edges * D_VEC + 255) / 256), 256>>>(
            input, sidx, tidx, enorm, esgn, out, n_edges);
    }
}